// round 1
// baseline (speedup 1.0000x reference)
#include <cuda_runtime.h>

// Problem constants (fixed by the dataset)
#define B_GRAPHS 256
#define NPG      128           // nodes per graph
#define N_TOT    (B_GRAPHS*NPG)   // 32768
#define FDIM     128
#define MLP_H    512
#define OUT_DIM  10

// ---------------- scratch (device globals; no allocation allowed) ----------
__device__ float g_A[(size_t)B_GRAPHS*NPG*NPG];   // 16 MB dense normalized adjacency
__device__ float g_buf1[(size_t)N_TOT*FDIM];      // 16 MB  (X@W result)
__device__ float g_buf2[(size_t)N_TOT*FDIM];      // 16 MB  (aggregated H)
__device__ float g_dinv[N_TOT];                   // degree count, then rsqrt
__device__ float g_mlp[B_GRAPHS*MLP_H];           // lin1 accumulator

// ---------------- zero scratch --------------------------------------------
__global__ void zero_scratch() {
    int i = blockIdx.x * 256 + threadIdx.x;       // grid 4096 -> i < 1,048,576
    float4 z = make_float4(0.f, 0.f, 0.f, 0.f);
    ((float4*)g_A)[i] = z;                        // 1,048,576 float4 = 16MB
    if (i < N_TOT/4)            ((float4*)g_dinv)[i] = z;
    if (i < B_GRAPHS*MLP_H/4)   ((float4*)g_mlp)[i]  = z;
}

// ---------------- degree / dinv -------------------------------------------
__global__ void deg_kernel(const int* __restrict__ dst, int E) {
    int e = blockIdx.x * 256 + threadIdx.x;
    if (e < E) atomicAdd(&g_dinv[dst[e]], 1.0f);
}
__global__ void dinv_kernel() {
    int i = blockIdx.x * 256 + threadIdx.x;
    if (i < N_TOT) g_dinv[i] = rsqrtf(g_dinv[i] + 1.0f);   // +1 = self loop
}

// ---------------- dense normalized adjacency ------------------------------
__global__ void build_A_edges(const int* __restrict__ src,
                              const int* __restrict__ dst, int E) {
    int e = blockIdx.x * 256 + threadIdx.x;
    if (e < E) {
        int s = src[e], d = dst[e];
        int b = d >> 7;
        // A[b][target][source] += dinv[s]*dinv[d]   (duplicates accumulate)
        atomicAdd(&g_A[(size_t)b*NPG*NPG + (size_t)(d & 127)*NPG + (s & 127)],
                  g_dinv[s] * g_dinv[d]);
    }
}
__global__ void build_A_self() {
    int n = blockIdx.x * 256 + threadIdx.x;
    if (n < N_TOT) {
        int b = n >> 7, i = n & 127;
        g_A[(size_t)b*NPG*NPG + (size_t)i*NPG + i] += g_dinv[n] * g_dinv[n];
    }
}

// ============ 128x128-tile fp32 GEMM kernels (256 thr, 8x8 micro) =========

// O[32768,128] = X[32768,128] @ W[128,128].  sel=0: X=Xext, sel=1: X=g_buf2.
__global__ void __launch_bounds__(256)
gemm_xw(const float* __restrict__ Xext, const float* __restrict__ W, int sel) {
    __shared__ __align__(16) float Ast[32][132];   // [k][row]
    __shared__ __align__(16) float Bs [32][132];   // [k][col]
    const float* __restrict__ X = sel ? g_buf2 : Xext;
    const int t = threadIdx.x;
    const int tx = t & 15, ty = t >> 4;
    const size_t row0 = (size_t)blockIdx.x * 128;

    float acc[8][8];
#pragma unroll
    for (int i = 0; i < 8; i++)
#pragma unroll
        for (int j = 0; j < 8; j++) acc[i][j] = 0.f;

    for (int kc = 0; kc < FDIM; kc += 32) {
#pragma unroll
        for (int q = 0; q < 4; q++) {             // X tile 128x32 (transposed)
            int idx = q * 256 + t;
            int r   = idx >> 3;
            int k4  = (idx & 7) << 2;
            float4 v = *(const float4*)(X + (row0 + r)*FDIM + kc + k4);
            Ast[k4+0][r] = v.x; Ast[k4+1][r] = v.y;
            Ast[k4+2][r] = v.z; Ast[k4+3][r] = v.w;
        }
#pragma unroll
        for (int q = 0; q < 4; q++) {             // W chunk 32x128
            int idx = q * 256 + t;
            int k   = idx >> 5;
            int c4  = (idx & 31) << 2;
            *(float4*)&Bs[k][c4] = *(const float4*)(W + (size_t)(kc+k)*FDIM + c4);
        }
        __syncthreads();
#pragma unroll
        for (int k = 0; k < 32; k++) {
            float a[8], b[8];
            *(float4*)&a[0] = *(const float4*)&Ast[k][ty*8];
            *(float4*)&a[4] = *(const float4*)&Ast[k][ty*8+4];
            *(float4*)&b[0] = *(const float4*)&Bs [k][tx*8];
            *(float4*)&b[4] = *(const float4*)&Bs [k][tx*8+4];
#pragma unroll
            for (int i = 0; i < 8; i++)
#pragma unroll
                for (int j = 0; j < 8; j++) acc[i][j] += a[i]*b[j];
        }
        __syncthreads();
    }
#pragma unroll
    for (int i = 0; i < 8; i++) {
        float4 v0 = make_float4(acc[i][0],acc[i][1],acc[i][2],acc[i][3]);
        float4 v1 = make_float4(acc[i][4],acc[i][5],acc[i][6],acc[i][7]);
        float* o = g_buf1 + (row0 + ty*8 + i)*FDIM + tx*8;
        *(float4*)o       = v0;
        *(float4*)(o + 4) = v1;
    }
}

// g_buf2[b] = relu( g_A[b] @ g_buf1[b] + bias )   one CTA per graph
__global__ void __launch_bounds__(256)
agg_gemm(const float* __restrict__ bias) {
    __shared__ __align__(16) float Ast[32][132];
    __shared__ __align__(16) float Bs [32][132];
    const int b = blockIdx.x;
    const float* __restrict__ A = g_A   + (size_t)b*NPG*NPG;
    const float* __restrict__ H = g_buf1 + (size_t)b*NPG*FDIM;
    float* __restrict__ O       = g_buf2 + (size_t)b*NPG*FDIM;
    const int t = threadIdx.x;
    const int tx = t & 15, ty = t >> 4;

    float acc[8][8];
#pragma unroll
    for (int i = 0; i < 8; i++)
#pragma unroll
        for (int j = 0; j < 8; j++) acc[i][j] = 0.f;

    for (int kc = 0; kc < NPG; kc += 32) {
#pragma unroll
        for (int q = 0; q < 4; q++) {
            int idx = q * 256 + t;
            int r   = idx >> 3;
            int k4  = (idx & 7) << 2;
            float4 v = *(const float4*)(A + (size_t)r*NPG + kc + k4);
            Ast[k4+0][r] = v.x; Ast[k4+1][r] = v.y;
            Ast[k4+2][r] = v.z; Ast[k4+3][r] = v.w;
        }
#pragma unroll
        for (int q = 0; q < 4; q++) {
            int idx = q * 256 + t;
            int k   = idx >> 5;
            int c4  = (idx & 31) << 2;
            *(float4*)&Bs[k][c4] = *(const float4*)(H + (size_t)(kc+k)*FDIM + c4);
        }
        __syncthreads();
#pragma unroll
        for (int k = 0; k < 32; k++) {
            float a[8], bb[8];
            *(float4*)&a[0]  = *(const float4*)&Ast[k][ty*8];
            *(float4*)&a[4]  = *(const float4*)&Ast[k][ty*8+4];
            *(float4*)&bb[0] = *(const float4*)&Bs [k][tx*8];
            *(float4*)&bb[4] = *(const float4*)&Bs [k][tx*8+4];
#pragma unroll
            for (int i = 0; i < 8; i++)
#pragma unroll
                for (int j = 0; j < 8; j++) acc[i][j] += a[i]*bb[j];
        }
        __syncthreads();
    }
    float bv[8];
    *(float4*)&bv[0] = *(const float4*)(bias + tx*8);
    *(float4*)&bv[4] = *(const float4*)(bias + tx*8 + 4);
#pragma unroll
    for (int i = 0; i < 8; i++) {
        float r[8];
#pragma unroll
        for (int j = 0; j < 8; j++) { float v = acc[i][j] + bv[j]; r[j] = v > 0.f ? v : 0.f; }
        float* o = O + (size_t)(ty*8 + i)*FDIM + tx*8;
        *(float4*)o       = make_float4(r[0],r[1],r[2],r[3]);
        *(float4*)(o + 4) = make_float4(r[4],r[5],r[6],r[7]);
    }
}

// g_mlp[256,512] += H2[256,16384] @ lin1_w[16384,512]  (split-K=32, atomics)
__global__ void __launch_bounds__(256)
lin1_gemm(const float* __restrict__ W) {
    __shared__ __align__(16) float Ast[32][132];
    __shared__ __align__(16) float Bs [32][132];
    const int col0 = blockIdx.x * 128;   // 0..3
    const int row0 = blockIdx.y * 128;   // 0..1
    const int k0   = blockIdx.z * 512;   // 0..31
    const float* __restrict__ H2 = g_buf2;  // [256,16384] (node-major == reshape)
    const int t = threadIdx.x;
    const int tx = t & 15, ty = t >> 4;

    float acc[8][8];
#pragma unroll
    for (int i = 0; i < 8; i++)
#pragma unroll
        for (int j = 0; j < 8; j++) acc[i][j] = 0.f;

    for (int kc = 0; kc < 512; kc += 32) {
#pragma unroll
        for (int q = 0; q < 4; q++) {
            int idx = q * 256 + t;
            int r   = idx >> 3;
            int k4  = (idx & 7) << 2;
            float4 v = *(const float4*)(H2 + (size_t)(row0 + r)*16384 + k0 + kc + k4);
            Ast[k4+0][r] = v.x; Ast[k4+1][r] = v.y;
            Ast[k4+2][r] = v.z; Ast[k4+3][r] = v.w;
        }
#pragma unroll
        for (int q = 0; q < 4; q++) {
            int idx = q * 256 + t;
            int k   = idx >> 5;
            int c4  = (idx & 31) << 2;
            *(float4*)&Bs[k][c4] =
                *(const float4*)(W + (size_t)(k0 + kc + k)*MLP_H + col0 + c4);
        }
        __syncthreads();
#pragma unroll
        for (int k = 0; k < 32; k++) {
            float a[8], b[8];
            *(float4*)&a[0] = *(const float4*)&Ast[k][ty*8];
            *(float4*)&a[4] = *(const float4*)&Ast[k][ty*8+4];
            *(float4*)&b[0] = *(const float4*)&Bs [k][tx*8];
            *(float4*)&b[4] = *(const float4*)&Bs [k][tx*8+4];
#pragma unroll
            for (int i = 0; i < 8; i++)
#pragma unroll
                for (int j = 0; j < 8; j++) acc[i][j] += a[i]*b[j];
        }
        __syncthreads();
    }
#pragma unroll
    for (int i = 0; i < 8; i++)
#pragma unroll
        for (int j = 0; j < 8; j++)
            atomicAdd(&g_mlp[(size_t)(row0 + ty*8 + i)*MLP_H + col0 + tx*8 + j],
                      acc[i][j]);
}

__global__ void relu_bias_kernel(const float* __restrict__ b) {
    int i = blockIdx.x * 256 + threadIdx.x;
    if (i < B_GRAPHS*MLP_H) {
        float v = g_mlp[i] + b[i & (MLP_H-1)];
        g_mlp[i] = v > 0.f ? v : 0.f;
    }
}

// out[256,10] = g_mlp @ lin2_w + lin2_b.   One CTA per row, one warp per col.
__global__ void __launch_bounds__(320)
lin2_gemm(const float* __restrict__ W, const float* __restrict__ bias,
          float* __restrict__ out) {
    __shared__ float xr[MLP_H];
    const int m = blockIdx.x;
    const int w = threadIdx.x >> 5;      // 0..9
    const int lane = threadIdx.x & 31;
    for (int i = threadIdx.x; i < MLP_H; i += 320) xr[i] = g_mlp[(size_t)m*MLP_H + i];
    __syncthreads();
    float s = 0.f;
    for (int k = lane; k < MLP_H; k += 32) s += xr[k] * W[(size_t)k*OUT_DIM + w];
#pragma unroll
    for (int o = 16; o; o >>= 1) s += __shfl_xor_sync(0xffffffffu, s, o);
    if (lane == 0) out[(size_t)m*OUT_DIM + w] = s + bias[w];
}

// ---------------------------------------------------------------------------
extern "C" void kernel_launch(void* const* d_in, const int* in_sizes, int n_in,
                              void* d_out, int out_size) {
    const float* x   = (const float*)d_in[0];
    const int*   ei  = (const int*)  d_in[1];
    // d_in[2] = batch (unused; implied by layout)
    const float* W1  = (const float*)d_in[3];
    const float* b1  = (const float*)d_in[4];
    const float* W2  = (const float*)d_in[5];
    const float* b2  = (const float*)d_in[6];
    const float* l1w = (const float*)d_in[7];
    const float* l1b = (const float*)d_in[8];
    const float* l2w = (const float*)d_in[9];
    const float* l2b = (const float*)d_in[10];
    float* out = (float*)d_out;

    const int E = in_sizes[1] / 2;
    const int* src = ei;
    const int* dst = ei + E;
    const int eg = (E + 255) / 256;

    zero_scratch  <<<4096, 256>>>();
    deg_kernel    <<<eg, 256>>>(dst, E);
    dinv_kernel   <<<N_TOT/256, 256>>>();
    build_A_edges <<<eg, 256>>>(src, dst, E);
    build_A_self  <<<N_TOT/256, 256>>>();

    // layer 1
    gemm_xw  <<<256, 256>>>(x, W1, 0);      // g_buf1 = x @ W1
    agg_gemm <<<256, 256>>>(b1);            // g_buf2 = relu(A@g_buf1 + b1)
    // layer 2
    gemm_xw  <<<256, 256>>>(x, W2, 1);      // g_buf1 = g_buf2 @ W2
    agg_gemm <<<256, 256>>>(b2);            // g_buf2 = relu(A@g_buf1 + b2) = H2

    // MLP
    lin1_gemm <<<dim3(4, 2, 32), 256>>>(l1w);
    relu_bias_kernel <<<(B_GRAPHS*MLP_H + 255)/256, 256>>>(l1b);
    lin2_gemm <<<B_GRAPHS, 320>>>(l2w, l2b, out);
}